// round 8
// baseline (speedup 1.0000x reference)
#include <cuda_runtime.h>
#include <cuda_fp16.h>
#include <cstdint>

#define B_SZ    8192
#define DK      128
#define EPSV    1e-6f
#define CEPS    (128.0f * 1e-6f * 1e-6f)
#define MARGINF 0.2f
#define QMAX    32512.0f

// int8 tiles: 128 rows x 128 bytes, stride 144 (16B pad).
// ldmatrix: each 8-lane matrix phase covers banks 4r..4r+3, r=0..7 -> all 32 banks, conflict-free.
#define RS      144
#define TIL     (128 * RS)               // 18432
#define SM_A    0                        // A hi tile; A lo at +TIL
#define OFF_LO  TIL
#define SM_B0   (2 * TIL)                // 36864
#define OFF_N2  (2 * TIL)                // within a B buffer (after hi+lo)
#define OFF_TG  (2 * TIL + 512)
#define BUFSZ   (2 * TIL + 640)          // 37504
#define SM_B1   (SM_B0 + BUFSZ)
#define SMEM_TOTAL (SM_B1 + BUFSZ)       // 111872

__device__ __align__(16) char     g_q1h[B_SZ * DK];
__device__ __align__(16) char     g_q1l[B_SZ * DK];
__device__ __align__(16) char     g_q2h[B_SZ * DK];
__device__ __align__(16) char     g_q2l[B_SZ * DK];
__device__ __align__(16) float    g_n1[B_SZ];
__device__ __align__(16) float    g_n2[B_SZ];
__device__ __align__(16) unsigned g_posmax[B_SZ];   // float bits; >=0 so uint order == float order
__device__ __align__(16) unsigned g_negmin[B_SZ];
__device__ __align__(16) char     g_tgt[B_SZ];
__device__ unsigned g_maxabs_u;   // zero-init at load; atomicMax of same data -> stable across replays
__device__ int      g_is32;

__device__ __forceinline__ uint32_t smem_u32(const void* p) {
    uint32_t a;
    asm("{ .reg .u64 t; cvta.to.shared.u64 t, %1; cvt.u32.u64 %0, t; }" : "=r"(a) : "l"(p));
    return a;
}

#define CPA16(d, s)  asm volatile("cp.async.cg.shared.global [%0], [%1], 16;" :: "r"(d), "l"(s))
#define CPCOMMIT()   asm volatile("cp.async.commit_group;" ::: "memory")
#define CPWAIT(n)    asm volatile("cp.async.wait_group %0;" :: "n"(n) : "memory")

#define LDSM4(r, addr)                                                          \
    asm volatile("ldmatrix.sync.aligned.m8n8.x4.shared.b16 {%0,%1,%2,%3}, [%4];" \
        : "=r"((r)[0]), "=r"((r)[1]), "=r"((r)[2]), "=r"((r)[3]) : "r"(addr))

#define IMMA(C, A, B0v, B1v)                                                    \
    asm volatile(                                                               \
        "mma.sync.aligned.m16n8k32.row.col.s32.s8.s8.s32 "                      \
        "{%0,%1,%2,%3}, {%4,%5,%6,%7}, {%8,%9}, {%0,%1,%2,%3};"                 \
        : "+r"((C)[0]), "+r"((C)[1]), "+r"((C)[2]), "+r"((C)[3])                \
        : "r"((A)[0]), "r"((A)[1]), "r"((A)[2]), "r"((A)[3]),                   \
          "r"(B0v), "r"(B1v))

// ---------------------------------------------------------------------------
// Kernel 0: global maxabs over both inputs + target dtype detect.
// ---------------------------------------------------------------------------
__global__ void stats_kernel(const float* __restrict__ e1, const float* __restrict__ e2,
                             const unsigned* __restrict__ tw) {
    float m = 0.0f;
    int idx = blockIdx.x * 256 + threadIdx.x;
    const float4* p1 = (const float4*)e1;
    const float4* p2 = (const float4*)e2;
    for (int i = idx; i < B_SZ * DK / 4; i += 512 * 256) {
        float4 a = p1[i];
        float4 b = p2[i];
        m = fmaxf(m, fmaxf(fmaxf(fabsf(a.x), fabsf(a.y)), fmaxf(fabsf(a.z), fabsf(a.w))));
        m = fmaxf(m, fmaxf(fmaxf(fabsf(b.x), fabsf(b.y)), fmaxf(fabsf(b.z), fabsf(b.w))));
    }
#pragma unroll
    for (int o = 16; o; o >>= 1) m = fmaxf(m, __shfl_xor_sync(0xFFFFFFFFu, m, o));
    if ((threadIdx.x & 31) == 0) atomicMax(&g_maxabs_u, __float_as_uint(m));

    if (blockIdx.x == 0) {
        __shared__ unsigned sred[8];
        unsigned acc = 0;
        for (int i = threadIdx.x; i < B_SZ / 2; i += 256) acc |= tw[2 * i + 1];
#pragma unroll
        for (int o = 16; o; o >>= 1) acc |= __shfl_xor_sync(0xFFFFFFFFu, acc, o);
        if ((threadIdx.x & 31) == 0) sred[threadIdx.x >> 5] = acc;
        __syncthreads();
        if (threadIdx.x == 0) {
            acc = 0;
            for (int i = 0; i < 8; i++) acc |= sred[i];
            g_is32 = (acc != 0);
        }
    }
}

// ---------------------------------------------------------------------------
// Kernel 1: quantize to int8 hi/lo planes + row norms + init + tgt decode.
// One warp per row.
// ---------------------------------------------------------------------------
__global__ void split_kernel(const float* __restrict__ e1, const float* __restrict__ e2,
                             const unsigned* __restrict__ tw) {
    int w   = threadIdx.x >> 5;
    int lid = threadIdx.x & 31;
    int r   = blockIdx.x * 8 + w;

    float K = QMAX / fmaxf(__uint_as_float(g_maxabs_u), 1e-20f);

    float4 a = ((const float4*)(e1 + (size_t)r * DK))[lid];
    float4 b = ((const float4*)(e2 + (size_t)r * DK))[lid];

    int qa[4] = { __float2int_rn(a.x * K), __float2int_rn(a.y * K),
                  __float2int_rn(a.z * K), __float2int_rn(a.w * K) };
    int qb[4] = { __float2int_rn(b.x * K), __float2int_rn(b.y * K),
                  __float2int_rn(b.z * K), __float2int_rn(b.w * K) };
    unsigned ahp = 0, alp = 0, bhp = 0, blp = 0;
#pragma unroll
    for (int i = 0; i < 4; i++) {
        int ha = (qa[i] + 128) >> 8;
        int la = qa[i] - (ha << 8);
        int hb = (qb[i] + 128) >> 8;
        int lb = qb[i] - (hb << 8);
        ahp |= (unsigned)(ha & 255) << (8 * i);
        alp |= (unsigned)(la & 255) << (8 * i);
        bhp |= (unsigned)(hb & 255) << (8 * i);
        blp |= (unsigned)(lb & 255) << (8 * i);
    }
    ((unsigned*)(g_q1h + (size_t)r * DK))[lid] = ahp;
    ((unsigned*)(g_q1l + (size_t)r * DK))[lid] = alp;
    ((unsigned*)(g_q2h + (size_t)r * DK))[lid] = bhp;
    ((unsigned*)(g_q2l + (size_t)r * DK))[lid] = blp;

    float s1 = a.x + a.y + a.z + a.w;
    float q1 = a.x * a.x + a.y * a.y + a.z * a.z + a.w * a.w;
    float s2 = b.x + b.y + b.z + b.w;
    float q2 = b.x * b.x + b.y * b.y + b.z * b.z + b.w * b.w;
#pragma unroll
    for (int o = 16; o; o >>= 1) {
        s1 += __shfl_xor_sync(0xFFFFFFFFu, s1, o);
        q1 += __shfl_xor_sync(0xFFFFFFFFu, q1, o);
        s2 += __shfl_xor_sync(0xFFFFFFFFu, s2, o);
        q2 += __shfl_xor_sync(0xFFFFFFFFu, q2, o);
    }
    if (lid == 0) {
        g_n1[r] = q1 + 2.0f * EPSV * s1;
        g_n2[r] = q2 - 2.0f * EPSV * s2;
        g_posmax[r] = 0u;
        g_negmin[r] = 0x7f800000u;
        g_tgt[r] = (char)(g_is32 ? tw[r] : tw[2 * r]);
    }
}

// ---------------------------------------------------------------------------
// B-chunk loader: 128 columns (int8 hi+lo rows of e2) + n2/tgt metadata.
// ---------------------------------------------------------------------------
__device__ __forceinline__ void load_b_chunk(uint32_t bb, int gcol0, int tid) {
    int row = tid & 127;
    int sel = tid >> 7;
    const char* src = (sel ? g_q2l : g_q2h) + (size_t)(gcol0 + row) * DK;
    uint32_t dst = bb + (uint32_t)sel * TIL + (uint32_t)row * RS;
#pragma unroll
    for (int i = 0; i < 8; i++) CPA16(dst + i * 16, src + i * 16);
    if (tid < 32) {
        CPA16(bb + OFF_N2 + tid * 16, (const char*)(g_n2 + gcol0) + tid * 16);
    } else if (tid < 40) {
        CPA16(bb + OFF_TG + (tid - 32) * 16, (const char*)(g_tgt + gcol0) + (tid - 32) * 16);
    }
}

// ---------------------------------------------------------------------------
// Kernel 2: int8 3-pass (HH, HL+LH) GEMM + fused masked row max/min.
// Grid (2, 64). 8 warps: wm=w&3 (rows), wn=w>>2 (64-col span, two 32-col halves).
// dot = (65536*HH + 256*CR) / K^2, exact s32 accumulation; LL term dropped.
// ---------------------------------------------------------------------------
__global__ void __launch_bounds__(256, 1) mma_kernel() {
    extern __shared__ char smem[];
    uint32_t sb = smem_u32(smem);
    int tid  = threadIdx.x;
    int w    = tid >> 5;
    int lane = tid & 31;
    int tq   = lane >> 2;
    int tr   = lane & 3;
    int wm   = w & 3;
    int wn   = w >> 2;
    int r0    = blockIdx.y * 128;
    int cbase = blockIdx.x * 4096;

    float sc   = __uint_as_float(g_maxabs_u) / QMAX;
    float m2k2 = -2.0f * sc * sc;

    // stage A tile (hi + lo)
    {
        int row = tid & 127;
        int sel = tid >> 7;
        const char* src = (sel ? g_q1l : g_q1h) + (size_t)(r0 + row) * DK;
        uint32_t dst = sb + SM_A + (uint32_t)sel * TIL + (uint32_t)row * RS;
#pragma unroll
        for (int i = 0; i < 8; i++) CPA16(dst + i * 16, src + i * 16);
    }
    CPCOMMIT();
    load_b_chunk(sb + SM_B0, cbase, tid);        CPCOMMIT();
    load_b_chunk(sb + SM_B1, cbase + 128, tid);  CPCOMMIT();

    CPWAIT(2);            // A staged
    __syncthreads();

    // A fragments (hi and lo) -> registers: 2 mt x 4 k32-steps x 4 regs each.
    uint32_t ahh[2][4][4], all[2][4][4];
    {
        uint32_t ab = sb + SM_A + (uint32_t)(wm * 32 + (lane & 15)) * RS + ((lane >> 4) << 4);
#pragma unroll
        for (int mt = 0; mt < 2; mt++)
#pragma unroll
            for (int ks = 0; ks < 4; ks++) {
                LDSM4(ahh[mt][ks], ab + mt * 16 * RS + ks * 32);
                LDSM4(all[mt][ks], ab + OFF_LO + mt * 16 * RS + ks * 32);
            }
    }

    float n1v[4], maxp[4], minn[4];
#pragma unroll
    for (int s = 0; s < 4; s++) {
        int grow = r0 + wm * 32 + (s >> 1) * 16 + tq + (s & 1) * 8;
        n1v[s]  = g_n1[grow];
        maxp[s] = 0.0f;
        minn[s] = __int_as_float(0x7f800000);
    }

    for (int j = 0; j < 32; j++) {
        uint32_t bb = sb + ((j & 1) ? SM_B1 : SM_B0);
        if (j < 31) { CPWAIT(1); } else { CPWAIT(0); }
        __syncthreads();

        const float* n2b = (const float*)(smem + ((j & 1) ? SM_B1 : SM_B0) + OFF_N2);
        const char*  tgb = (const char*)(smem + ((j & 1) ? SM_B1 : SM_B0) + OFF_TG);

#pragma unroll
        for (int h01 = 0; h01 < 2; h01++) {
            int hh[2][4][4], cr[2][4][4];
#pragma unroll
            for (int mt = 0; mt < 2; mt++)
#pragma unroll
                for (int nt = 0; nt < 4; nt++)
#pragma unroll
                    for (int i = 0; i < 4; i++) { hh[mt][nt][i] = 0; cr[mt][nt][i] = 0; }

            uint32_t bbase = bb + (uint32_t)(wn * 64 + h01 * 32 + (lane & 15)) * RS
                           + ((lane >> 4) << 4);
#pragma unroll
            for (int ks = 0; ks < 4; ks++) {
                uint32_t bhf[2][4], blf[2][4];
                LDSM4(bhf[0], bbase + ks * 32);
                LDSM4(bhf[1], bbase + 16 * RS + ks * 32);
                LDSM4(blf[0], bbase + OFF_LO + ks * 32);
                LDSM4(blf[1], bbase + OFF_LO + 16 * RS + ks * 32);
#pragma unroll
                for (int mt = 0; mt < 2; mt++)
#pragma unroll
                    for (int pp = 0; pp < 2; pp++)
#pragma unroll
                        for (int qq = 0; qq < 2; qq++) {
                            int nt = pp * 2 + qq;
                            IMMA(hh[mt][nt], ahh[mt][ks], bhf[pp][qq], bhf[pp][qq + 2]);
                            IMMA(cr[mt][nt], ahh[mt][ks], blf[pp][qq], blf[pp][qq + 2]);
                            IMMA(cr[mt][nt], all[mt][ks], bhf[pp][qq], bhf[pp][qq + 2]);
                        }
            }

            // fold this 32-col half into per-row max/min registers
#pragma unroll
            for (int nt = 0; nt < 4; nt++) {
                int jl0 = wn * 64 + h01 * 32 + nt * 8 + tr * 2;
#pragma unroll
                for (int b = 0; b < 2; b++) {
                    float n2v = n2b[jl0 + b];
                    char  tv  = tgb[jl0 + b];
#pragma unroll
                    for (int mt = 0; mt < 2; mt++)
#pragma unroll
                        for (int hx = 0; hx < 2; hx++) {
                            int i = hx * 2 + b;
                            int s = mt * 2 + hx;
                            float dotf = fmaf(65536.0f, (float)hh[mt][nt][i],
                                              256.0f * (float)cr[mt][nt][i]);
                            float sq = fmaxf(fmaf(m2k2, dotf, n1v[s] + n2v) + CEPS, 0.0f);
                            if (tv) maxp[s] = fmaxf(maxp[s], sq);
                            else    minn[s] = fminf(minn[s], sq);
                        }
                }
            }
        }

        __syncthreads();      // all warps done with this buffer (data + meta)
        if (j + 2 < 32) {
            load_b_chunk(bb, cbase + (j + 2) * 128, tid);
            CPCOMMIT();
        }
    }

    // merge quad lanes (xor 1,2 share the row) + one atomic per row-slot
#pragma unroll
    for (int s = 0; s < 4; s++) {
#pragma unroll
        for (int o = 1; o <= 2; o <<= 1) {
            maxp[s] = fmaxf(maxp[s], __shfl_xor_sync(0xFFFFFFFFu, maxp[s], o));
            minn[s] = fminf(minn[s], __shfl_xor_sync(0xFFFFFFFFu, minn[s], o));
        }
        if (tr == 0) {
            int grow = r0 + wm * 32 + (s >> 1) * 16 + tq + (s & 1) * 8;
            atomicMax(&g_posmax[grow], __float_as_uint(maxp[s]));
            atomicMin(&g_negmin[grow], __float_as_uint(minn[s]));
        }
    }
}

// ---------------------------------------------------------------------------
// Kernel 3: final scalar reduction over anchors (target == 1).
// ---------------------------------------------------------------------------
__global__ void final_kernel(float* __restrict__ out) {
    __shared__ float ss[32];
    __shared__ float sc[32];
    int tid = threadIdx.x;
    float s = 0.0f, c = 0.0f;
#pragma unroll 8
    for (int i = tid; i < B_SZ; i += 1024) {
        if (g_tgt[i]) {
            float pm = __uint_as_float(g_posmax[i]);
            float nm = __uint_as_float(g_negmin[i]);
            float v  = sqrtf(pm) - sqrtf(nm) + MARGINF;
            s += fmaxf(v, 0.0f);
            c += 1.0f;
        }
    }
#pragma unroll
    for (int o = 16; o; o >>= 1) {
        s += __shfl_xor_sync(0xFFFFFFFFu, s, o);
        c += __shfl_xor_sync(0xFFFFFFFFu, c, o);
    }
    if ((tid & 31) == 0) { ss[tid >> 5] = s; sc[tid >> 5] = c; }
    __syncthreads();
    if (tid < 32) {
        s = ss[tid];
        c = sc[tid];
#pragma unroll
        for (int o = 16; o; o >>= 1) {
            s += __shfl_xor_sync(0xFFFFFFFFu, s, o);
            c += __shfl_xor_sync(0xFFFFFFFFu, c, o);
        }
        if (tid == 0) out[0] = s / c;
    }
}

extern "C" void kernel_launch(void* const* d_in, const int* in_sizes, int n_in,
                              void* d_out, int out_size) {
    const float*    e1 = (const float*)d_in[0];
    const float*    e2 = (const float*)d_in[1];
    const unsigned* tw = (const unsigned*)d_in[2];
    float* out = (float*)d_out;

    cudaFuncSetAttribute(mma_kernel, cudaFuncAttributeMaxDynamicSharedMemorySize, SMEM_TOTAL);

    stats_kernel<<<512, 256>>>(e1, e2, tw);
    split_kernel<<<B_SZ / 8, 256>>>(e1, e2, tw);
    mma_kernel<<<dim3(2, 64), 256, SMEM_TOTAL>>>();
    final_kernel<<<1, 1024>>>(out);
}

// round 9
// speedup vs baseline: 4.5749x; 4.5749x over previous
#include <cuda_runtime.h>
#include <cuda_fp16.h>
#include <cstdint>

#define B_SZ    8192
#define DK      128
#define EPSV    1e-6f
#define CEPS    (128.0f * 1e-6f * 1e-6f)
#define MARGINF 0.2f

// fp16 tiles: 128 rows x 128 halfs, row stride 272 B (256 + 16 pad)
// -> row start word = 68r mod 32 = 4r mod 32: conflict-free ldmatrix (proven in R7).
#define RSTRIDE 272
#define TILE_B  (128 * RSTRIDE)            // 34816
#define SM_A    0                          // A hi tile
#define SM_B0   TILE_B                     // 34816
#define OFF_N2  TILE_B                     // within a B buffer: after data
#define OFF_TG  (TILE_B + 512)
#define BUFSZ   (TILE_B + 640)             // 35456
#define SM_B1   (SM_B0 + BUFSZ)
#define SMEM_TOTAL (SM_B1 + BUFSZ)         // 105728

__device__ __align__(16) __half   g_e1h[B_SZ * DK];
__device__ __align__(16) __half   g_e2h[B_SZ * DK];
__device__ __align__(16) float    g_n1[B_SZ];
__device__ __align__(16) float    g_n2[B_SZ];
__device__ __align__(16) unsigned g_posmax[B_SZ];   // float bits; >=0 so uint order == float order
__device__ __align__(16) unsigned g_negmin[B_SZ];
__device__ __align__(16) char     g_tgt[B_SZ];
__device__ int      g_is32;

__device__ __forceinline__ uint32_t smem_u32(const void* p) {
    uint32_t a;
    asm("{ .reg .u64 t; cvta.to.shared.u64 t, %1; cvt.u32.u64 %0, t; }" : "=r"(a) : "l"(p));
    return a;
}

#define CPA16(d, s)  asm volatile("cp.async.cg.shared.global [%0], [%1], 16;" :: "r"(d), "l"(s))
#define CPCOMMIT()   asm volatile("cp.async.commit_group;" ::: "memory")
#define CPWAIT(n)    asm volatile("cp.async.wait_group %0;" :: "n"(n) : "memory")

#define LDSM4(r, addr)                                                          \
    asm volatile("ldmatrix.sync.aligned.m8n8.x4.shared.b16 {%0,%1,%2,%3}, [%4];" \
        : "=r"((r)[0]), "=r"((r)[1]), "=r"((r)[2]), "=r"((r)[3]) : "r"(addr))

#define MMA(C, A, B0v, B1v)                                                     \
    asm volatile(                                                               \
        "mma.sync.aligned.m16n8k16.row.col.f32.f16.f16.f32 "                    \
        "{%0,%1,%2,%3}, {%4,%5,%6,%7}, {%8,%9}, {%0,%1,%2,%3};"                 \
        : "+f"((C)[0]), "+f"((C)[1]), "+f"((C)[2]), "+f"((C)[3])                \
        : "r"((A)[0]), "r"((A)[1]), "r"((A)[2]), "r"((A)[3]),                   \
          "r"(B0v), "r"(B1v))

// ---------------------------------------------------------------------------
// Kernel 0: detect target dtype (int32 vs int64) by OR of odd 32-bit words.
// ---------------------------------------------------------------------------
__global__ void detect_kernel(const unsigned* __restrict__ w) {
    __shared__ unsigned sred[32];
    unsigned acc = 0;
    for (int i = threadIdx.x; i < B_SZ / 2; i += 1024) acc |= w[2 * i + 1];
#pragma unroll
    for (int o = 16; o; o >>= 1) acc |= __shfl_xor_sync(0xFFFFFFFFu, acc, o);
    if ((threadIdx.x & 31) == 0) sred[threadIdx.x >> 5] = acc;
    __syncthreads();
    if (threadIdx.x < 32) {
        acc = sred[threadIdx.x];
#pragma unroll
        for (int o = 16; o; o >>= 1) acc |= __shfl_xor_sync(0xFFFFFFFFu, acc, o);
        if (threadIdx.x == 0) g_is32 = (acc != 0);
    }
}

// ---------------------------------------------------------------------------
// Kernel 1: fp32 -> fp16 convert + row norms + init + tgt decode. One warp/row.
// ---------------------------------------------------------------------------
__global__ void split_kernel(const float* __restrict__ e1, const float* __restrict__ e2,
                             const unsigned* __restrict__ tw) {
    int w   = threadIdx.x >> 5;
    int lid = threadIdx.x & 31;
    int r   = blockIdx.x * 8 + w;

    float4 a = ((const float4*)(e1 + (size_t)r * DK))[lid];
    float4 b = ((const float4*)(e2 + (size_t)r * DK))[lid];

    __half2 a0 = __floats2half2_rn(a.x, a.y), a1 = __floats2half2_rn(a.z, a.w);
    __half2 b0 = __floats2half2_rn(b.x, b.y), b1 = __floats2half2_rn(b.z, b.w);
    ((uint2*)(g_e1h + (size_t)r * DK))[lid] = make_uint2(*(uint32_t*)&a0, *(uint32_t*)&a1);
    ((uint2*)(g_e2h + (size_t)r * DK))[lid] = make_uint2(*(uint32_t*)&b0, *(uint32_t*)&b1);

    float s1 = a.x + a.y + a.z + a.w;
    float q1 = a.x * a.x + a.y * a.y + a.z * a.z + a.w * a.w;
    float s2 = b.x + b.y + b.z + b.w;
    float q2 = b.x * b.x + b.y * b.y + b.z * b.z + b.w * b.w;
#pragma unroll
    for (int o = 16; o; o >>= 1) {
        s1 += __shfl_xor_sync(0xFFFFFFFFu, s1, o);
        q1 += __shfl_xor_sync(0xFFFFFFFFu, q1, o);
        s2 += __shfl_xor_sync(0xFFFFFFFFu, s2, o);
        q2 += __shfl_xor_sync(0xFFFFFFFFu, q2, o);
    }
    if (lid == 0) {
        g_n1[r] = q1 + 2.0f * EPSV * s1;
        g_n2[r] = q2 - 2.0f * EPSV * s2;
        g_posmax[r] = 0u;
        g_negmin[r] = 0x7f800000u;
        g_tgt[r] = (char)(g_is32 ? tw[r] : tw[2 * r]);
    }
}

// ---------------------------------------------------------------------------
// B-chunk loader: 128 columns (fp16 rows of e2) + n2/tgt metadata.
// ---------------------------------------------------------------------------
__device__ __forceinline__ void load_b_chunk(uint32_t bb, int gcol0, int tid) {
    int row  = tid >> 1;
    int h128 = (tid & 1) * 128;
    const char* src = (const char*)(g_e2h + (size_t)(gcol0 + row) * DK) + h128;
    uint32_t dst = bb + (uint32_t)row * RSTRIDE + h128;
#pragma unroll
    for (int i = 0; i < 8; i++) CPA16(dst + i * 16, src + i * 16);
    if (tid < 32) {
        CPA16(bb + OFF_N2 + tid * 16, (const char*)(g_n2 + gcol0) + tid * 16);
    } else if (tid < 40) {
        CPA16(bb + OFF_TG + (tid - 32) * 16, (const char*)(g_tgt + gcol0) + (tid - 32) * 16);
    }
}

// ---------------------------------------------------------------------------
// Kernel 2: single-pass fp16 GEMM + fused masked row max/min.
// Grid (2, 64). 8 warps: wm=w&3 (rows wm*32..+32), wn=w>>2 (cols wn*64..+64).
// A fragments register-resident; B double-buffered via cp.async.
// Epilogue tracks t = n2 - 2*dot; n1 + CEPS + clamp applied once at the end.
// ---------------------------------------------------------------------------
__global__ void __launch_bounds__(256, 1) mma_kernel() {
    extern __shared__ char smem[];
    uint32_t sb = smem_u32(smem);
    int tid  = threadIdx.x;
    int w    = tid >> 5;
    int lane = tid & 31;
    int tq   = lane >> 2;
    int tr   = lane & 3;
    int wm   = w & 3;
    int wn   = w >> 2;
    int r0    = blockIdx.y * 128;
    int cbase = blockIdx.x * 4096;

    // stage A tile
    {
        int row  = tid >> 1;
        int h128 = (tid & 1) * 128;
        const char* src = (const char*)(g_e1h + (size_t)(r0 + row) * DK) + h128;
        uint32_t dst = sb + SM_A + (uint32_t)row * RSTRIDE + h128;
#pragma unroll
        for (int i = 0; i < 8; i++) CPA16(dst + i * 16, src + i * 16);
    }
    CPCOMMIT();
    load_b_chunk(sb + SM_B0, cbase, tid);        CPCOMMIT();
    load_b_chunk(sb + SM_B1, cbase + 128, tid);  CPCOMMIT();

    CPWAIT(2);            // A staged
    __syncthreads();

    // A fragments -> registers (2 mt x 8 ksteps x 4 regs)
    uint32_t ahr[2][8][4];
    {
        uint32_t abase = sb + SM_A + (uint32_t)(wm * 32 + (lane & 15)) * RSTRIDE
                       + ((lane >> 4) << 4);
#pragma unroll
        for (int mt = 0; mt < 2; mt++)
#pragma unroll
            for (int ks = 0; ks < 8; ks++)
                LDSM4(ahr[mt][ks], abase + mt * 16 * RSTRIDE + ks * 32);
    }

    float maxp[4], minn[4];
#pragma unroll
    for (int s = 0; s < 4; s++) {
        maxp[s] = __int_as_float(0xff800000);   // -inf
        minn[s] = __int_as_float(0x7f800000);   // +inf
    }

    for (int j = 0; j < 32; j++) {
        uint32_t bb = sb + ((j & 1) ? SM_B1 : SM_B0);
        if (j < 31) { CPWAIT(1); } else { CPWAIT(0); }
        __syncthreads();

        float c[2][8][4];
#pragma unroll
        for (int mt = 0; mt < 2; mt++)
#pragma unroll
            for (int nt = 0; nt < 8; nt++)
#pragma unroll
                for (int i = 0; i < 4; i++) c[mt][nt][i] = 0.0f;

        uint32_t bbase = bb + (uint32_t)(wn * 64 + (lane & 15)) * RSTRIDE
                       + ((lane >> 4) << 4);
#pragma unroll
        for (int ks = 0; ks < 8; ks++) {
            uint32_t bh[4][4];
#pragma unroll
            for (int p = 0; p < 4; p++) LDSM4(bh[p], bbase + p * 16 * RSTRIDE + ks * 32);
#pragma unroll
            for (int mt = 0; mt < 2; mt++)
#pragma unroll
                for (int p = 0; p < 4; p++) {
                    MMA(c[mt][2 * p],     ahr[mt][ks], bh[p][0], bh[p][2]);
                    MMA(c[mt][2 * p + 1], ahr[mt][ks], bh[p][1], bh[p][3]);
                }
        }

        // fold chunk: t = n2 - 2*dot; track max over positives / min over negatives
        const float* n2b = (const float*)(smem + ((j & 1) ? SM_B1 : SM_B0) + OFF_N2);
        const char*  tgb = (const char*)(smem + ((j & 1) ? SM_B1 : SM_B0) + OFF_TG);
#pragma unroll
        for (int nt = 0; nt < 8; nt++)
#pragma unroll
            for (int b = 0; b < 2; b++) {
                int jl = wn * 64 + nt * 8 + tr * 2 + b;
                float n2v = n2b[jl];
                char  tv  = tgb[jl];
#pragma unroll
                for (int mt = 0; mt < 2; mt++)
#pragma unroll
                    for (int hx = 0; hx < 2; hx++) {
                        float t = fmaf(-2.0f, c[mt][nt][hx * 2 + b], n2v);
                        int s = mt * 2 + hx;
                        if (tv) maxp[s] = fmaxf(maxp[s], t);
                        else    minn[s] = fminf(minn[s], t);
                    }
            }

        __syncthreads();      // all warps done with this buffer
        if (j + 2 < 32) {
            load_b_chunk(bb, cbase + (j + 2) * 128, tid);
            CPCOMMIT();
        }
    }

    // merge quad lanes, apply n1 + CEPS + clamp once, one atomic per row-slot
#pragma unroll
    for (int s = 0; s < 4; s++) {
#pragma unroll
        for (int o = 1; o <= 2; o <<= 1) {
            maxp[s] = fmaxf(maxp[s], __shfl_xor_sync(0xFFFFFFFFu, maxp[s], o));
            minn[s] = fminf(minn[s], __shfl_xor_sync(0xFFFFFFFFu, minn[s], o));
        }
        if (tr == 0) {
            int grow = r0 + wm * 32 + (s >> 1) * 16 + tq + (s & 1) * 8;
            float n1v = g_n1[grow];
            float pm = fmaxf(n1v + maxp[s] + CEPS, 0.0f);   // -inf -> 0 (harmless vs init 0)
            float nm = fmaxf(n1v + minn[s] + CEPS, 0.0f);   // +inf stays +inf
            atomicMax(&g_posmax[grow], __float_as_uint(pm));
            atomicMin(&g_negmin[grow], __float_as_uint(nm));
        }
    }
}

// ---------------------------------------------------------------------------
// Kernel 3: final scalar reduction over anchors (target == 1).
// ---------------------------------------------------------------------------
__global__ void final_kernel(float* __restrict__ out) {
    __shared__ float ss[32];
    __shared__ float sc[32];
    int tid = threadIdx.x;
    float s = 0.0f, c = 0.0f;
#pragma unroll 8
    for (int i = tid; i < B_SZ; i += 1024) {
        if (g_tgt[i]) {
            float pm = __uint_as_float(g_posmax[i]);
            float nm = __uint_as_float(g_negmin[i]);
            float v  = sqrtf(pm) - sqrtf(nm) + MARGINF;
            s += fmaxf(v, 0.0f);
            c += 1.0f;
        }
    }
#pragma unroll
    for (int o = 16; o; o >>= 1) {
        s += __shfl_xor_sync(0xFFFFFFFFu, s, o);
        c += __shfl_xor_sync(0xFFFFFFFFu, c, o);
    }
    if ((tid & 31) == 0) { ss[tid >> 5] = s; sc[tid >> 5] = c; }
    __syncthreads();
    if (tid < 32) {
        s = ss[tid];
        c = sc[tid];
#pragma unroll
        for (int o = 16; o; o >>= 1) {
            s += __shfl_xor_sync(0xFFFFFFFFu, s, o);
            c += __shfl_xor_sync(0xFFFFFFFFu, c, o);
        }
        if (tid == 0) out[0] = s / c;
    }
}

extern "C" void kernel_launch(void* const* d_in, const int* in_sizes, int n_in,
                              void* d_out, int out_size) {
    const float*    e1 = (const float*)d_in[0];
    const float*    e2 = (const float*)d_in[1];
    const unsigned* tw = (const unsigned*)d_in[2];
    float* out = (float*)d_out;

    cudaFuncSetAttribute(mma_kernel, cudaFuncAttributeMaxDynamicSharedMemorySize, SMEM_TOTAL);

    detect_kernel<<<1, 1024>>>(tw);
    split_kernel<<<B_SZ / 8, 256>>>(e1, e2, tw);
    mma_kernel<<<dim3(2, 64), 256, SMEM_TOTAL>>>();
    final_kernel<<<1, 1024>>>(out);
}